// round 13
// baseline (speedup 1.0000x reference)
#include <cuda_runtime.h>

#define NTHREADS 128

// Species row 0 = H, row 1 = O (padded: mu=0, sg=1)
__constant__ float c_mu[2][9] = {
  {-0.0013891633279463555f, 0.052817133273316774f, 0.139812833597163f, 0.04197082575153015f,
    0.f, 0.f, 0.f, 0.f, 0.f},
  { 0.3869724094534165f, 1.1195726605859562f, 4.597656411500856f, 4.18116756869605f,
   -0.777753667038269f, 0.8991094564592526f, 0.25287442792706855f, 0.f, 0.f}
};
__constant__ float c_sg[2][9] = {
  {0.014984132924379046f, 0.06597323056314336f, 0.05229082868259066f, 0.10317217531939492f,
   1.f, 1.f, 1.f, 1.f, 1.f},
  {0.01648580936203453f, 0.04360467004470585f, 0.10939958699162289f, 0.1452881891452822f,
   0.24744978852384295f, 0.6757096584771374f, 0.15629951845443388f, 1.f, 1.f}
};

// om vector -> coefficient indices. Vectors 0-3: p (9+3v+k).
// Vectors 4-7: d[v-4][{0,2,5}] (D_REORDER[0:3] = 0,2,5), vectors 8-11: d[v-8][{4,3,1}].
__constant__ int c_omidx[12][3] = {
  { 9, 10, 11}, {12, 13, 14}, {15, 16, 17}, {18, 19, 20},
  {21, 23, 26}, {27, 29, 32}, {33, 35, 38}, {39, 41, 44},
  {25, 24, 22}, {31, 30, 28}, {37, 36, 34}, {43, 42, 40}
};

// triu_indices(12, k=1) row-major
__constant__ unsigned char c_pi[66] = {
  0,0,0,0,0,0,0,0,0,0,0,
  1,1,1,1,1,1,1,1,1,1,
  2,2,2,2,2,2,2,2,2,
  3,3,3,3,3,3,3,3,
  4,4,4,4,4,4,4,
  5,5,5,5,5,5,
  6,6,6,6,6,
  7,7,7,7,
  8,8,8,
  9,9,
  10
};
__constant__ unsigned char c_pj[66] = {
  1,2,3,4,5,6,7,8,9,10,11,
  2,3,4,5,6,7,8,9,10,11,
  3,4,5,6,7,8,9,10,11,
  4,5,6,7,8,9,10,11,
  5,6,7,8,9,10,11,
  6,7,8,9,10,11,
  7,8,9,10,11,
  8,9,10,11,
  9,10,11,
  10,11,
  11
};

// cos/sin of Z_k = k*pi/7, k = 0..7
__constant__ float c_cz[8] = { 1.0f,  0.90096887f,  0.62348980f,  0.22252093f,
                              -0.22252093f, -0.62348980f, -0.90096887f, -1.0f };
__constant__ float c_sz[8] = { 0.0f,  0.43388374f,  0.78183148f,  0.97492791f,
                               0.97492791f,  0.78183148f,  0.43388374f,  0.0f };

// 256-bit global store (sm_100+). PTX: .v8 is only legal with .b32, so pass
// the float bit patterns through "r" constraints.
__device__ __forceinline__ void stg256(float* p, float4 a, float4 b) {
    asm volatile("st.global.v8.b32 [%0], {%1,%2,%3,%4,%5,%6,%7,%8};"
        :: "l"(p),
           "r"(__float_as_uint(a.x)), "r"(__float_as_uint(a.y)),
           "r"(__float_as_uint(a.z)), "r"(__float_as_uint(a.w)),
           "r"(__float_as_uint(b.x)), "r"(__float_as_uint(b.y)),
           "r"(__float_as_uint(b.z)), "r"(__float_as_uint(b.w)) : "memory");
}

__global__ __launch_bounds__(NTHREADS)
void aev_kernel(const float* __restrict__ coeff, const int* __restrict__ species,
                float* __restrict__ out)
{
    __shared__ float sh_sn[9];                      // normalized s coefficients
    __shared__ float sh_dist[12];
    __shared__ float sh_u[12][3];
    __shared__ float sh_c[66], sh_sq[66], sh_av[66];
    __shared__ __align__(32) float sh_sr[336];      // 144 s_aev + 192 r_aev
    __shared__ float sh_f1[528];                    // 2*f1 (premultiplied), [pair][z]
    __shared__ __align__(32) float sh_f2[528];      // [pair][a], 8-float rows = 32B

    const int blk = blockIdx.x;      // one block per atom
    const int t   = threadIdx.x;
    const float* cin = coeff + (size_t)blk * 45;

    // ---- stage 1: om vectors / distances / unit vectors + normalized s ----
    if (t < 12) {
        float x = cin[c_omidx[t][0]];
        float y = cin[c_omidx[t][1]];
        float z = cin[c_omidx[t][2]];
        float dot = fmaf(x, x, fmaf(y, y, z * z));
        float d   = sqrtf(dot);
        bool zm = (fabsf(x) < 1e-12f) && (fabsf(y) < 1e-12f) && (fabsf(z) < 1e-12f);
        float inv = zm ? 0.0f : rsqrtf(dot);
        sh_dist[t] = d;
        sh_u[t][0] = x * inv;
        sh_u[t][1] = y * inv;
        sh_u[t][2] = z * inv;
    } else if (t >= 32 && t < 41) {
        int k  = t - 32;
        int sp = (species[blk] == 8) ? 1 : 0;
        sh_sn[k] = (cin[k] - c_mu[sp][k]) / c_sg[sp][k];
    }
    __syncthreads();

    // ---- stage 2: per-pair cos(theta), sin(theta), avg distance ----
    if (t < 66) {
        int i = c_pi[t], j = c_pj[t];
        float c = 0.9999f * fmaf(sh_u[i][0], sh_u[j][0],
                      fmaf(sh_u[i][1], sh_u[j][1], sh_u[i][2] * sh_u[j][2]));
        sh_c[t]  = c;
        sh_sq[t] = sqrtf(fmaxf(0.0f, fmaf(-c, c, 1.0f)));   // sin(acos(c))
        sh_av[t] = 0.5f * (sh_dist[i] + sh_dist[j]);
    }
    __syncthreads();

    // ---- stage 3: fully parallel element evaluation (1392 independent) ----
    // [0,144)    s_aev:  k=w/16, i=w%16,  exp(-4*(sn[k] - (-4 + i*8/15))^2)
    // [144,336)  r_aev:  k, i,            exp(-4*(dist[k] - i*2/15)^2)
    // [336,864)  f2:     p=v/8, a=v%8,    exp(-8*(av[p] - a*2/7)^2)
    // [864,1392) f1:     p, z,            2*((1 + cos(theta - Z_z))/2)^8
    #pragma unroll
    for (int it = 0; it < 11; ++it) {
        int w = it * 128 + t;
        if (w < 144) {
            int k = w >> 4, i = w & 15;
            float x = sh_sn[k] - fmaf((float)i, 0.53333333f, -4.0f);
            sh_sr[w] = __expf(-4.0f * x * x);
        } else if (w < 336) {
            int v = w - 144; int k = v >> 4, i = v & 15;
            float x = sh_dist[k] - (float)i * 0.13333333f;
            sh_sr[w] = __expf(-4.0f * x * x);
        } else if (w < 864) {
            int v = w - 336; int p = v >> 3, a = v & 7;
            float x = sh_av[p] - (float)a * 0.28571429f;
            sh_f2[v] = __expf(-8.0f * x * x);
        } else if (w < 1392) {
            int v = w - 864; int p = v >> 3, z = v & 7;
            float ct = fmaf(sh_c[p], c_cz[z], sh_sq[p] * c_sz[z]);  // cos(theta - Z_z)
            float b  = fmaf(0.5f, ct, 0.5f);
            float b2 = b * b;
            float b4 = b2 * b2;
            sh_f1[v] = 2.0f * (b4 * b4);
        }
    }
    __syncthreads();

    // ---- stage 4: 256-bit stores. 570 v8 rows per atom:
    //   [0,42)    s+r:      out[w*8 .. w*8+7] = sh_sr[w*8 ..]
    //   [42,570)  angular:  rel=w-42, pair=rel/8, z=rel%8,
    //             out[336 + rel*8 + a] = f1[pair][z] * f2[pair][a], a=0..7
    float* outp = out + (size_t)blk * 4560;
    const float4* srv = reinterpret_cast<const float4*>(sh_sr);
    const float4* f2v = reinterpret_cast<const float4*>(sh_f2);
    #pragma unroll
    for (int it = 0; it < 5; ++it) {
        int w = it * 128 + t;
        if (w < 42) {
            stg256(outp + w * 8, srv[w * 2], srv[w * 2 + 1]);
        } else if (w < 570) {
            int rel  = w - 42;
            int pair = rel >> 3;
            float f1 = sh_f1[rel];                 // rel = pair*8 + z
            float4 a = f2v[pair * 2];
            float4 b = f2v[pair * 2 + 1];
            a.x *= f1; a.y *= f1; a.z *= f1; a.w *= f1;
            b.x *= f1; b.y *= f1; b.z *= f1; b.w *= f1;
            stg256(outp + 336 + rel * 8, a, b);    // pair*64 + z*8 = rel*8
        }
    }
}

extern "C" void kernel_launch(void* const* d_in, const int* in_sizes, int n_in,
                              void* d_out, int out_size)
{
    const float* coeff   = (const float*)d_in[0];   // (nconf, natoms, 45) f32
    const int*   species = (const int*)d_in[1];     // (nconf, natoms) i32
    float*       out     = (float*)d_out;           // (nconf, natoms, 4560) f32
    int nblk = in_sizes[1];                         // nconf * natoms atoms
    aev_kernel<<<nblk, NTHREADS>>>(coeff, species, out);
}

// round 14
// speedup vs baseline: 1.4033x; 1.4033x over previous
#include <cuda_runtime.h>

#define NTHREADS 256   // two 128-thread halves, one atom each

// Species row 0 = H, row 1 = O (padded: mu=0, sg=1)
__constant__ float c_mu[2][9] = {
  {-0.0013891633279463555f, 0.052817133273316774f, 0.139812833597163f, 0.04197082575153015f,
    0.f, 0.f, 0.f, 0.f, 0.f},
  { 0.3869724094534165f, 1.1195726605859562f, 4.597656411500856f, 4.18116756869605f,
   -0.777753667038269f, 0.8991094564592526f, 0.25287442792706855f, 0.f, 0.f}
};
__constant__ float c_sg[2][9] = {
  {0.014984132924379046f, 0.06597323056314336f, 0.05229082868259066f, 0.10317217531939492f,
   1.f, 1.f, 1.f, 1.f, 1.f},
  {0.01648580936203453f, 0.04360467004470585f, 0.10939958699162289f, 0.1452881891452822f,
   0.24744978852384295f, 0.6757096584771374f, 0.15629951845443388f, 1.f, 1.f}
};

// om vector -> coefficient indices. Vectors 0-3: p (9+3v+k).
// Vectors 4-7: d[v-4][{0,2,5}] (D_REORDER[0:3] = 0,2,5), vectors 8-11: d[v-8][{4,3,1}].
__constant__ int c_omidx[12][3] = {
  { 9, 10, 11}, {12, 13, 14}, {15, 16, 17}, {18, 19, 20},
  {21, 23, 26}, {27, 29, 32}, {33, 35, 38}, {39, 41, 44},
  {25, 24, 22}, {31, 30, 28}, {37, 36, 34}, {43, 42, 40}
};

// triu_indices(12, k=1) row-major
__constant__ unsigned char c_pi[66] = {
  0,0,0,0,0,0,0,0,0,0,0,
  1,1,1,1,1,1,1,1,1,1,
  2,2,2,2,2,2,2,2,2,
  3,3,3,3,3,3,3,3,
  4,4,4,4,4,4,4,
  5,5,5,5,5,5,
  6,6,6,6,6,
  7,7,7,7,
  8,8,8,
  9,9,
  10
};
__constant__ unsigned char c_pj[66] = {
  1,2,3,4,5,6,7,8,9,10,11,
  2,3,4,5,6,7,8,9,10,11,
  3,4,5,6,7,8,9,10,11,
  4,5,6,7,8,9,10,11,
  5,6,7,8,9,10,11,
  6,7,8,9,10,11,
  7,8,9,10,11,
  8,9,10,11,
  9,10,11,
  10,11,
  11
};

// cos/sin of Z_k = k*pi/7, k = 0..7
__constant__ float c_cz[8] = { 1.0f,  0.90096887f,  0.62348980f,  0.22252093f,
                              -0.22252093f, -0.62348980f, -0.90096887f, -1.0f };
__constant__ float c_sz[8] = { 0.0f,  0.43388374f,  0.78183148f,  0.97492791f,
                               0.97492791f,  0.78183148f,  0.43388374f,  0.0f };

__global__ __launch_bounds__(NTHREADS)
void aev_kernel(const float* __restrict__ coeff, const int* __restrict__ species,
                float* __restrict__ out, int nblk)
{
    // Two independent per-atom banks; halves share the block barriers.
    __shared__ float sh_sn[2][9];
    __shared__ float sh_dist[2][12];
    __shared__ float sh_u[2][12][3];
    __shared__ float sh_c[2][66], sh_sq[2][66], sh_av[2][66];
    __shared__ __align__(16) float sh_sr[2][336];   // 144 s_aev + 192 r_aev
    __shared__ float sh_f1[2][528];                 // 2*f1 (premultiplied), [pair][z]
    __shared__ __align__(16) float sh_f2[2][528];   // [pair][a]

    const int t    = threadIdx.x;
    const int h    = t >> 7;           // which half / atom slot
    const int tt   = t & 127;          // thread id within half
    const int atom = blockIdx.x * 2 + h;
    const bool valid = atom < nblk;
    const int ald  = valid ? atom : (nblk - 1);     // clamped for loads
    const float* cin = coeff + (size_t)ald * 45;

    // ---- stage 1: om vectors / distances / unit vectors + normalized s ----
    if (tt < 12) {
        float x = cin[c_omidx[tt][0]];
        float y = cin[c_omidx[tt][1]];
        float z = cin[c_omidx[tt][2]];
        float dot = fmaf(x, x, fmaf(y, y, z * z));
        float d   = sqrtf(dot);
        bool zm = (fabsf(x) < 1e-12f) && (fabsf(y) < 1e-12f) && (fabsf(z) < 1e-12f);
        float inv = zm ? 0.0f : rsqrtf(dot);
        sh_dist[h][tt] = d;
        sh_u[h][tt][0] = x * inv;
        sh_u[h][tt][1] = y * inv;
        sh_u[h][tt][2] = z * inv;
    } else if (tt >= 32 && tt < 41) {
        int k  = tt - 32;
        int sp = (species[ald] == 8) ? 1 : 0;
        sh_sn[h][k] = (cin[k] - c_mu[sp][k]) / c_sg[sp][k];
    }
    __syncthreads();

    // ---- stage 2: per-pair cos(theta), sin(theta), avg distance ----
    if (tt < 66) {
        int i = c_pi[tt], j = c_pj[tt];
        float c = 0.9999f * fmaf(sh_u[h][i][0], sh_u[h][j][0],
                      fmaf(sh_u[h][i][1], sh_u[h][j][1], sh_u[h][i][2] * sh_u[h][j][2]));
        sh_c[h][tt]  = c;
        sh_sq[h][tt] = sqrtf(fmaxf(0.0f, fmaf(-c, c, 1.0f)));   // sin(acos(c))
        sh_av[h][tt] = 0.5f * (sh_dist[h][i] + sh_dist[h][j]);
    }
    __syncthreads();

    // ---- stage 3: fully parallel element evaluation (1392 independent) ----
    // [0,144)    s_aev:  k=w/16, i=w%16,  exp(-4*(sn[k] - (-4 + i*8/15))^2)
    // [144,336)  r_aev:  k, i,            exp(-4*(dist[k] - i*2/15)^2)
    // [336,864)  f2:     p=v/8, a=v%8,    exp(-8*(av[p] - a*2/7)^2)
    // [864,1392) f1:     p, z,            2*((1 + cos(theta - Z_z))/2)^8
    #pragma unroll
    for (int it = 0; it < 11; ++it) {
        int w = it * 128 + tt;
        if (w < 144) {
            int k = w >> 4, i = w & 15;
            float x = sh_sn[h][k] - fmaf((float)i, 0.53333333f, -4.0f);
            sh_sr[h][w] = __expf(-4.0f * x * x);
        } else if (w < 336) {
            int v = w - 144; int k = v >> 4, i = v & 15;
            float x = sh_dist[h][k] - (float)i * 0.13333333f;
            sh_sr[h][w] = __expf(-4.0f * x * x);
        } else if (w < 864) {
            int v = w - 336; int p = v >> 3, a = v & 7;
            float x = sh_av[h][p] - (float)a * 0.28571429f;
            sh_f2[h][v] = __expf(-8.0f * x * x);
        } else if (w < 1392) {
            int v = w - 864; int p = v >> 3, z = v & 7;
            float ct = fmaf(sh_c[h][p], c_cz[z], sh_sq[h][p] * c_sz[z]);  // cos(theta - Z_z)
            float b  = fmaf(0.5f, ct, 0.5f);
            float b2 = b * b;
            float b4 = b2 * b2;
            sh_f1[h][v] = 2.0f * (b4 * b4);
        }
    }
    __syncthreads();

    // ---- stage 4: coalesced float4 stores: 84 (s+r) + 1056 angular per atom ----
    if (valid) {
        float4* out4 = reinterpret_cast<float4*>(out) + (size_t)atom * 1140;
        if (tt < 84) out4[tt] = reinterpret_cast<const float4*>(sh_sr[h])[tt];

        const float4* f2v = reinterpret_cast<const float4*>(sh_f2[h]);
        #pragma unroll
        for (int it = 0; it < 9; ++it) {
            int w = it * 128 + tt;
            if (w < 1056) {
                int pair = w >> 4;
                int rem  = w & 15;                           // = z*2 + half
                float f1 = sh_f1[h][pair * 8 + (rem >> 1)];  // includes the 2x
                float4 f2 = f2v[pair * 2 + (rem & 1)];
                float4 o;
                o.x = f1 * f2.x; o.y = f1 * f2.y; o.z = f1 * f2.z; o.w = f1 * f2.w;
                out4[84 + w] = o;                            // 336 + pair*64 + z*8 + a
            }
        }
    }
}

extern "C" void kernel_launch(void* const* d_in, const int* in_sizes, int n_in,
                              void* d_out, int out_size)
{
    const float* coeff   = (const float*)d_in[0];   // (nconf, natoms, 45) f32
    const int*   species = (const int*)d_in[1];     // (nconf, natoms) i32
    float*       out     = (float*)d_out;           // (nconf, natoms, 4560) f32
    int nblk = in_sizes[1];                         // nconf * natoms atoms
    int grid = (nblk + 1) / 2;                      // 2 atoms per block
    aev_kernel<<<grid, NTHREADS>>>(coeff, species, out, nblk);
}